// round 4
// baseline (speedup 1.0000x reference)
#include <cuda_runtime.h>
#include <math.h>

#define N_B 64
#define T_T 512
#define D_D 512
#define H_H 512

// 67 MB scratch for xWx (device global: allocation-free per harness rules)
__device__ float g_xwx[(size_t)N_B * T_T * H_H];
__device__ int g_sync[8];

__global__ void init_sync_kernel() {
    if (threadIdx.x < 8) g_sync[threadIdx.x] = 0;
}

// ---------------------------------------------------------------------------
// Phase 1: g_xwx[m][h] = x[m][:] @ Wx[:][h] + b[h],  m = n*T + t  (32768 x 512)
// Classic 128x128x16 SGEMM, 8x8 register tiles, 256 threads.
// ---------------------------------------------------------------------------
#define BM 128
#define BN 128
#define BK 16

__global__ __launch_bounds__(256, 2) void xwx_gemm_kernel(
    const float* __restrict__ A,    // (32768, 512) = x
    const float* __restrict__ B,    // (512, 512)   = Wx
    const float* __restrict__ bias) // (512,)
{
    __shared__ float As[BK][BM + 4];   // transposed A tile
    __shared__ float Bs[BK][BN + 4];

    const int tid = threadIdx.x;
    const int bm = blockIdx.y * BM;
    const int bn = blockIdx.x * BN;

    const int ty = tid >> 4;      // 0..15
    const int tx = tid & 15;      // 0..15

    const int aRow = tid >> 2;          // 0..63
    const int aCol = (tid & 3) << 2;    // 0,4,8,12
    const int bRow = tid >> 5;          // 0..7
    const int bCol = (tid & 31) << 2;   // 0..124

    float acc[8][8];
#pragma unroll
    for (int i = 0; i < 8; i++)
#pragma unroll
        for (int j = 0; j < 8; j++) acc[i][j] = 0.f;

    for (int kt = 0; kt < D_D; kt += BK) {
#pragma unroll
        for (int rr = 0; rr < BM; rr += 64) {
            float4 a = *(const float4*)&A[(size_t)(bm + aRow + rr) * D_D + kt + aCol];
            As[aCol + 0][aRow + rr] = a.x;
            As[aCol + 1][aRow + rr] = a.y;
            As[aCol + 2][aRow + rr] = a.z;
            As[aCol + 3][aRow + rr] = a.w;
        }
#pragma unroll
        for (int rr = 0; rr < BK; rr += 8) {
            float4 b4 = *(const float4*)&B[(size_t)(kt + bRow + rr) * H_H + bn + bCol];
            *(float4*)&Bs[bRow + rr][bCol] = b4;
        }
        __syncthreads();

#pragma unroll
        for (int k = 0; k < BK; k++) {
            float4 a0 = *(const float4*)&As[k][ty * 4];
            float4 a1 = *(const float4*)&As[k][64 + ty * 4];
            float4 b0 = *(const float4*)&Bs[k][tx * 4];
            float4 b1 = *(const float4*)&Bs[k][64 + tx * 4];
            float av[8] = {a0.x, a0.y, a0.z, a0.w, a1.x, a1.y, a1.z, a1.w};
            float bv[8] = {b0.x, b0.y, b0.z, b0.w, b1.x, b1.y, b1.z, b1.w};
#pragma unroll
            for (int i = 0; i < 8; i++)
#pragma unroll
                for (int j = 0; j < 8; j++)
                    acc[i][j] += av[i] * bv[j];
        }
        __syncthreads();
    }

#pragma unroll
    for (int i = 0; i < 8; i++) {
        int row = bm + ((i < 4) ? (ty * 4 + i) : (64 + ty * 4 + (i - 4)));
#pragma unroll
        for (int jj = 0; jj < 2; jj++) {
            int col = bn + jj * 64 + tx * 4;
            float4 v;
            v.x = acc[i][jj * 4 + 0] + bias[col + 0];
            v.y = acc[i][jj * 4 + 1] + bias[col + 1];
            v.z = acc[i][jj * 4 + 2] + bias[col + 2];
            v.w = acc[i][jj * 4 + 3] + bias[col + 3];
            *(float4*)&g_xwx[(size_t)row * H_H + col] = v;
        }
    }
}

// ---------------------------------------------------------------------------
// Phase 2: persistent scan. 128 CTAs = 8 batch-groups (8 rows each) x 16
// column-slice CTAs (32 cols each). Wh slice SMEM-resident for whole kernel.
// Per-group 16-CTA atomic barrier per step; `out` doubles as h exchange buffer.
// ---------------------------------------------------------------------------
#define HPAD 516           // 512 + 4 pad (kills 8-way bank conflict on h reads)
#define RPAD 288           // 8*36 per-kp reduction row

__global__ __launch_bounds__(256, 1) void rnn_scan_kernel(
    const float* __restrict__ h0,   // (64, 512)
    const float* __restrict__ Wh,   // (512, 512)
    float* __restrict__ out)        // (64, 512, 512) = (N, T, H)
{
    extern __shared__ float smem[];
    float* sWh  = smem;                  // 512*32 floats
    float* sH   = sWh + 512 * 32;        // 8*HPAD floats
    float* sRed = sH + 8 * HPAD;         // 16*RPAD floats

    const int tid = threadIdx.x;
    const int g  = blockIdx.x >> 4;      // batch group 0..7
    const int c  = blockIdx.x & 15;      // column slice 0..15
    const int c0 = c << 5;
    const int n0 = g << 3;

    // Load Wh column slice once: sWh[k*32 + j] = Wh[k][c0+j]
    for (int i = tid; i < 512 * 32; i += 256) {
        int k = i >> 5, j = i & 31;
        sWh[i] = Wh[(size_t)k * H_H + c0 + j];
    }

    const int r   = tid & 7;             // batch row within group
    const int cg  = (tid >> 3) & 1;      // column half (16 cols)
    const int kp  = tid >> 4;            // k-split 0..15
    const int k0  = kp << 5;
    const int or_ = tid >> 5;            // output row for reduce phase
    const int oc  = tid & 31;            // output col for reduce phase

    for (int t = 0; t < T_T; t++) {
        // ---- load h_{t-1} (group's 8 rows) into SMEM, L2-coherent ----
        {
            const float* base = (t == 0)
                ? (h0 + (size_t)n0 * H_H)
                : (out + ((size_t)n0 * T_T + (t - 1)) * H_H);
            const size_t rstride = (t == 0) ? (size_t)H_H : (size_t)T_T * H_H;
#pragma unroll
            for (int i = tid; i < 1024; i += 256) {       // 8 rows * 128 float4
                int rr = i >> 7, q = i & 127;
                float4 v = __ldcg((const float4*)(base + rr * rstride) + q);
                *(float4*)&sH[rr * HPAD + (q << 2)] = v;
            }
        }
        // prefetch this CTA/thread's xwx value early (independent of h)
        const size_t oidx = ((size_t)(n0 + or_) * T_T + t) * H_H + c0 + oc;
        float xv = g_xwx[oidx];
        __syncthreads();

        // ---- FMA slab: acc[16 cols] over k-range of 32 ----
        float acc[16];
#pragma unroll
        for (int j = 0; j < 16; j++) acc[j] = 0.f;

#pragma unroll 8
        for (int kk = 0; kk < 32; kk++) {
            int k = k0 + kk;
            float hv = sH[r * HPAD + k];
            const float4* w = (const float4*)&sWh[(k << 5) + (cg << 4)];
            float4 w0 = w[0], w1 = w[1], w2 = w[2], w3 = w[3];
            acc[0]  += hv * w0.x;  acc[1]  += hv * w0.y;
            acc[2]  += hv * w0.z;  acc[3]  += hv * w0.w;
            acc[4]  += hv * w1.x;  acc[5]  += hv * w1.y;
            acc[6]  += hv * w1.z;  acc[7]  += hv * w1.w;
            acc[8]  += hv * w2.x;  acc[9]  += hv * w2.y;
            acc[10] += hv * w2.z;  acc[11] += hv * w2.w;
            acc[12] += hv * w3.x;  acc[13] += hv * w3.y;
            acc[14] += hv * w3.z;  acc[15] += hv * w3.w;
        }

        // ---- write partials for k-split reduction ----
        {
            float* dst = &sRed[kp * RPAD + r * 36 + (cg << 4)];
#pragma unroll
            for (int q = 0; q < 4; q++)
                *(float4*)&dst[q << 2] =
                    make_float4(acc[q * 4 + 0], acc[q * 4 + 1],
                                acc[q * 4 + 2], acc[q * 4 + 3]);
        }
        __syncthreads();

        // ---- reduce 16 partials, add xwx, tanh, store h_t ----
        {
            float v = 0.f;
#pragma unroll
            for (int p = 0; p < 16; p++)
                v += sRed[p * RPAD + or_ * 36 + oc];
            v = tanhf(v + xv);
            __stcg(&out[oidx], v);
        }

        // ---- per-group barrier (skip after final step) ----
        if (t < T_T - 1) {
            __threadfence();
            __syncthreads();
            if (tid == 0) {
                atomicAdd(&g_sync[g], 1);
                const int target = (t + 1) << 4;
                while (((volatile int*)g_sync)[g] < target) { }
            }
            __syncthreads();
        }
    }
}

// ---------------------------------------------------------------------------
extern "C" void kernel_launch(void* const* d_in, const int* in_sizes, int n_in,
                              void* d_out, int out_size) {
    (void)in_sizes; (void)n_in; (void)out_size;
    const float* x  = (const float*)d_in[0];
    const float* h0 = (const float*)d_in[1];
    const float* Wx = (const float*)d_in[2];
    const float* Wh = (const float*)d_in[3];
    const float* b  = (const float*)d_in[4];
    float* out = (float*)d_out;

    init_sync_kernel<<<1, 32>>>();

    dim3 g1(H_H / BN, (N_B * T_T) / BM);   // (4, 256)
    xwx_gemm_kernel<<<g1, 256>>>(x, Wx, b);

    const int smem_bytes = (512 * 32 + 8 * HPAD + 16 * RPAD) * (int)sizeof(float);
    cudaFuncSetAttribute((const void*)rnn_scan_kernel,
                         cudaFuncAttributeMaxDynamicSharedMemorySize, smem_bytes);
    rnn_scan_kernel<<<128, 256, smem_bytes>>>(h0, Wh, out);
}

// round 5
// speedup vs baseline: 1.0391x; 1.0391x over previous
#include <cuda_runtime.h>
#include <math.h>

#define N_B 64
#define T_T 512
#define D_D 512
#define H_H 512

// 67 MB scratch for xWx (device global: allocation-free per harness rules)
__device__ float g_xwx[(size_t)N_B * T_T * H_H];
__device__ int g_sync[8];

__global__ void init_sync_kernel() {
    if (threadIdx.x < 8) g_sync[threadIdx.x] = 0;
}

// ---- packed fp32x2 helpers (Blackwell FFMA2 path: 2 FMA lanes / issue) ----
__device__ __forceinline__ unsigned long long ffma2(
    unsigned long long a, unsigned long long b, unsigned long long c) {
    unsigned long long d;
    asm("fma.rn.f32x2 %0, %1, %2, %3;" : "=l"(d) : "l"(a), "l"(b), "l"(c));
    return d;
}
__device__ __forceinline__ unsigned long long fadd2(
    unsigned long long a, unsigned long long b) {
    unsigned long long d;
    asm("add.rn.f32x2 %0, %1, %2;" : "=l"(d) : "l"(a), "l"(b));
    return d;
}
__device__ __forceinline__ unsigned long long pack2(float lo, float hi) {
    unsigned long long r;
    asm("mov.b64 %0, {%1, %2};" : "=l"(r) : "f"(lo), "f"(hi));
    return r;
}

// ---------------------------------------------------------------------------
// Phase 1: g_xwx[m][h] = x[m][:] @ Wx[:][h] + b[h],  m = n*T + t  (32768 x 512)
// 128x128x16 SGEMM, 8x8 register tiles via f32x2 packed FMA, 256 threads.
// ---------------------------------------------------------------------------
#define BM 128
#define BN 128
#define BK 16

__global__ __launch_bounds__(256, 2) void xwx_gemm_kernel(
    const float* __restrict__ A,    // (32768, 512) = x
    const float* __restrict__ B,    // (512, 512)   = Wx
    const float* __restrict__ bias) // (512,)
{
    __shared__ float As[BK][BM + 4];   // transposed A tile
    __shared__ float Bs[BK][BN + 4];

    const int tid = threadIdx.x;
    const int bm = blockIdx.y * BM;
    const int bn = blockIdx.x * BN;

    const int ty = tid >> 4;      // 0..15
    const int tx = tid & 15;      // 0..15

    const int aRow = tid >> 2;          // 0..63
    const int aCol = (tid & 3) << 2;    // 0,4,8,12
    const int bRow = tid >> 5;          // 0..7
    const int bCol = (tid & 31) << 2;   // 0..124

    // acc2[i][j]: row i (8 rows), j = packed col pair:
    //   j=0: cols tx*4+{0,1}   j=1: tx*4+{2,3}
    //   j=2: 64+tx*4+{0,1}     j=3: 64+tx*4+{2,3}
    unsigned long long acc2[8][4];
#pragma unroll
    for (int i = 0; i < 8; i++)
#pragma unroll
        for (int j = 0; j < 4; j++) acc2[i][j] = 0ull;

    for (int kt = 0; kt < D_D; kt += BK) {
#pragma unroll
        for (int rr = 0; rr < BM; rr += 64) {
            float4 a = *(const float4*)&A[(size_t)(bm + aRow + rr) * D_D + kt + aCol];
            As[aCol + 0][aRow + rr] = a.x;
            As[aCol + 1][aRow + rr] = a.y;
            As[aCol + 2][aRow + rr] = a.z;
            As[aCol + 3][aRow + rr] = a.w;
        }
#pragma unroll
        for (int rr = 0; rr < BK; rr += 8) {
            float4 b4 = *(const float4*)&B[(size_t)(kt + bRow + rr) * H_H + bn + bCol];
            *(float4*)&Bs[bRow + rr][bCol] = b4;
        }
        __syncthreads();

#pragma unroll
        for (int k = 0; k < BK; k++) {
            float4 a0 = *(const float4*)&As[k][ty * 4];
            float4 a1 = *(const float4*)&As[k][64 + ty * 4];
            // Bs rows are 16B aligned: (BN+4)*4 = 528 bytes = 33*16
            ulonglong2 b01 = *(const ulonglong2*)&Bs[k][tx * 4];
            ulonglong2 b23 = *(const ulonglong2*)&Bs[k][64 + tx * 4];

            unsigned long long av[8];
            av[0] = pack2(a0.x, a0.x); av[1] = pack2(a0.y, a0.y);
            av[2] = pack2(a0.z, a0.z); av[3] = pack2(a0.w, a0.w);
            av[4] = pack2(a1.x, a1.x); av[5] = pack2(a1.y, a1.y);
            av[6] = pack2(a1.z, a1.z); av[7] = pack2(a1.w, a1.w);

#pragma unroll
            for (int i = 0; i < 8; i++) {
                acc2[i][0] = ffma2(av[i], b01.x, acc2[i][0]);
                acc2[i][1] = ffma2(av[i], b01.y, acc2[i][1]);
                acc2[i][2] = ffma2(av[i], b23.x, acc2[i][2]);
                acc2[i][3] = ffma2(av[i], b23.y, acc2[i][3]);
            }
        }
        __syncthreads();
    }

#pragma unroll
    for (int i = 0; i < 8; i++) {
        int row = bm + ((i < 4) ? (ty * 4 + i) : (64 + ty * 4 + (i - 4)));
#pragma unroll
        for (int jj = 0; jj < 2; jj++) {
            int col = bn + jj * 64 + tx * 4;
            ulonglong2 bb = *(const ulonglong2*)&bias[col];
            ulonglong2 v;
            v.x = fadd2(acc2[i][jj * 2 + 0], bb.x);
            v.y = fadd2(acc2[i][jj * 2 + 1], bb.y);
            *(ulonglong2*)&g_xwx[(size_t)row * H_H + col] = v;
        }
    }
}

// ---------------------------------------------------------------------------
// Phase 2: persistent scan. 128 CTAs = 8 batch-groups (8 rows each) x 16
// column-slice CTAs (32 cols each). Wh slice SMEM-resident for whole kernel.
// Inner slab uses f32x2 packed FMA (8 FFMA2 per k instead of 16 FFMA).
// ---------------------------------------------------------------------------
#define HPAD 516           // 512 + 4 pad
#define RPAD 288           // 8*36 per-kp reduction row

__global__ __launch_bounds__(256, 1) void rnn_scan_kernel(
    const float* __restrict__ h0,   // (64, 512)
    const float* __restrict__ Wh,   // (512, 512)
    float* __restrict__ out)        // (64, 512, 512) = (N, T, H)
{
    extern __shared__ float smem[];
    float* sWh  = smem;                  // 512*32 floats
    float* sH   = sWh + 512 * 32;        // 8*HPAD floats
    float* sRed = sH + 8 * HPAD;         // 16*RPAD floats

    const int tid = threadIdx.x;
    const int g  = blockIdx.x >> 4;      // batch group 0..7
    const int c  = blockIdx.x & 15;      // column slice 0..15
    const int c0 = c << 5;
    const int n0 = g << 3;

    // Load Wh column slice once: sWh[k*32 + j] = Wh[k][c0+j]
    for (int i = tid; i < 512 * 32; i += 256) {
        int k = i >> 5, j = i & 31;
        sWh[i] = Wh[(size_t)k * H_H + c0 + j];
    }

    const int r   = tid & 7;             // batch row within group
    const int cg  = (tid >> 3) & 1;      // column half (16 cols)
    const int kp  = tid >> 4;            // k-split 0..15
    const int k0  = kp << 5;
    const int or_ = tid >> 5;            // output row for reduce phase
    const int oc  = tid & 31;            // output col for reduce phase

    for (int t = 0; t < T_T; t++) {
        // ---- load h_{t-1} (group's 8 rows) into SMEM, L2-coherent ----
        {
            const float* base = (t == 0)
                ? (h0 + (size_t)n0 * H_H)
                : (out + ((size_t)n0 * T_T + (t - 1)) * H_H);
            const size_t rstride = (t == 0) ? (size_t)H_H : (size_t)T_T * H_H;
#pragma unroll
            for (int i = tid; i < 1024; i += 256) {       // 8 rows * 128 float4
                int rr = i >> 7, q = i & 127;
                float4 v = __ldcg((const float4*)(base + rr * rstride) + q);
                *(float4*)&sH[rr * HPAD + (q << 2)] = v;
            }
        }
        // prefetch this thread's xwx value early (independent of h)
        const size_t oidx = ((size_t)(n0 + or_) * T_T + t) * H_H + c0 + oc;
        float xv = g_xwx[oidx];
        __syncthreads();

        // ---- packed FMA slab: 8 x f32x2 accumulators = 16 cols ----
        unsigned long long acc2[8];
#pragma unroll
        for (int j = 0; j < 8; j++) acc2[j] = 0ull;

#pragma unroll 8
        for (int kk = 0; kk < 32; kk++) {
            int k = k0 + kk;
            float hv = sH[r * HPAD + k];
            unsigned long long h2 = pack2(hv, hv);
            const float* wp = &sWh[(k << 5) + (cg << 4)];   // 64B aligned
            ulonglong2 wa = *(const ulonglong2*)(wp + 0);
            ulonglong2 wb = *(const ulonglong2*)(wp + 4);
            ulonglong2 wc = *(const ulonglong2*)(wp + 8);
            ulonglong2 wd = *(const ulonglong2*)(wp + 12);
            acc2[0] = ffma2(h2, wa.x, acc2[0]);
            acc2[1] = ffma2(h2, wa.y, acc2[1]);
            acc2[2] = ffma2(h2, wb.x, acc2[2]);
            acc2[3] = ffma2(h2, wb.y, acc2[3]);
            acc2[4] = ffma2(h2, wc.x, acc2[4]);
            acc2[5] = ffma2(h2, wc.y, acc2[5]);
            acc2[6] = ffma2(h2, wd.x, acc2[6]);
            acc2[7] = ffma2(h2, wd.y, acc2[7]);
        }

        // ---- write partials for k-split reduction (bit-identical layout) ----
        {
            float* dst = &sRed[kp * RPAD + r * 36 + (cg << 4)];  // 16B aligned
            *(ulonglong2*)&dst[0]  = make_ulonglong2(acc2[0], acc2[1]);
            *(ulonglong2*)&dst[4]  = make_ulonglong2(acc2[2], acc2[3]);
            *(ulonglong2*)&dst[8]  = make_ulonglong2(acc2[4], acc2[5]);
            *(ulonglong2*)&dst[12] = make_ulonglong2(acc2[6], acc2[7]);
        }
        __syncthreads();

        // ---- reduce 16 partials, add xwx, tanh, store h_t ----
        {
            float v = 0.f;
#pragma unroll
            for (int p = 0; p < 16; p++)
                v += sRed[p * RPAD + or_ * 36 + oc];
            v = tanhf(v + xv);
            __stcg(&out[oidx], v);
        }

        // ---- per-group barrier (skip after final step) ----
        if (t < T_T - 1) {
            __threadfence();
            __syncthreads();
            if (tid == 0) {
                atomicAdd(&g_sync[g], 1);
                const int target = (t + 1) << 4;
                while (((volatile int*)g_sync)[g] < target) { }
            }
            __syncthreads();
        }
    }
}

// ---------------------------------------------------------------------------
extern "C" void kernel_launch(void* const* d_in, const int* in_sizes, int n_in,
                              void* d_out, int out_size) {
    (void)in_sizes; (void)n_in; (void)out_size;
    const float* x  = (const float*)d_in[0];
    const float* h0 = (const float*)d_in[1];
    const float* Wx = (const float*)d_in[2];
    const float* Wh = (const float*)d_in[3];
    const float* b  = (const float*)d_in[4];
    float* out = (float*)d_out;

    init_sync_kernel<<<1, 32>>>();

    dim3 g1(H_H / BN, (N_B * T_T) / BM);   // (4, 256)
    xwx_gemm_kernel<<<g1, 256>>>(x, Wx, b);

    const int smem_bytes = (512 * 32 + 8 * HPAD + 16 * RPAD) * (int)sizeof(float);
    cudaFuncSetAttribute((const void*)rnn_scan_kernel,
                         cudaFuncAttributeMaxDynamicSharedMemorySize, smem_bytes);
    rnn_scan_kernel<<<128, 256, smem_bytes>>>(h0, Wh, out);
}